// round 14
// baseline (speedup 1.0000x reference)
#include <cuda_runtime.h>
#include <cuda_fp16.h>
#include <cstdint>

// ============================================================
// WeightOnlyInt8Linear: out = input @ weight^T * scales
// R14: R12 base + warp-granular mbarrier pipeline.
//   R13 lost to per-thread arrive serialization (128 ATOMS/ktile
//   on one address). R14: empty[s] count=4, ONE elected-lane
//   arrive per warp; full[s] armed by async-proxy per-thread
//   cp.async.mbarrier.arrive.noinc (off critical path); waits
//   are read-only all-lane polls.
// Rest identical to R12: warp 64x64, 128-thr CTA, occ 2,
// CTA 128x128x64, 3 stages, chunked cp.async, paired-B LDS.128.
// ============================================================

static constexpr int MDIM = 8192;
static constexpr int NDIM = 4096;
static constexpr int KDIM = 4096;

static constexpr int BM = 128;
static constexpr int BN = 128;
static constexpr int BK = 64;             // 4 k16 steps
static constexpr int NKT = KDIM / BK;     // 64

static constexpr int A_ST_BYTES = (BM / 16) * (BK / 16) * 512;   // 16384
static constexpr int B_ST_BYTES = (BN / 8) * (BK / 16) * 256;    // 16384
static constexpr int STAGE_BYTES = A_ST_BYTES + B_ST_BYTES;      // 32768
static constexpr int HDR_BYTES   = 128;
static constexpr int SMEM_BYTES  = HDR_BYTES + 3 * STAGE_BYTES;  // 98432

// static scratch (fragment-major fp16)
__device__ __half g_af[(size_t)MDIM * KDIM];   // 64 MB: [m16][k16][512B]
__device__ __half g_wf[(size_t)NDIM * KDIM];   // 32 MB: [n8][k16-PAIR][512B]

// ---------------- helpers ----------------
__device__ __forceinline__ uint32_t smem_u32(const void* p) {
    uint32_t a;
    asm("{ .reg .u64 t; cvta.to.shared.u64 t, %1; cvt.u32.u64 %0, t; }"
        : "=r"(a) : "l"(p));
    return a;
}
__device__ __forceinline__ void cp_async16(uint32_t dst, const void* src) {
    asm volatile("cp.async.cg.shared.global [%0], [%1], 16;"
                 :: "r"(dst), "l"(src) : "memory");
}

#define MBAR_INIT(addr, cnt) \
    asm volatile("mbarrier.init.shared.b64 [%0], %1;" :: "r"(addr), "r"(cnt) : "memory")
#define MBAR_ARRIVE(addr) \
    asm volatile("mbarrier.arrive.shared.b64 _, [%0];" :: "r"(addr) : "memory")
#define CPASYNC_MBAR_ARRIVE(addr) \
    asm volatile("cp.async.mbarrier.arrive.noinc.shared.b64 [%0];" :: "r"(addr) : "memory")

#define MBAR_WAIT_PARITY(addr, ph) do {                                         \
    uint32_t _m = (addr); uint32_t _p = (ph); uint32_t _done;                   \
    asm volatile("{\n\t.reg .pred p;\n\t"                                       \
        "mbarrier.try_wait.parity.acquire.cta.shared::cta.b64 p, [%1], %2;\n\t" \
        "selp.b32 %0, 1, 0, p;\n\t}"                                            \
        : "=r"(_done) : "r"(_m), "r"(_p) : "memory");                           \
    if (!_done) {                                                               \
        asm volatile("{\n\t.reg .pred P1;\n\t"                                  \
            "WL_%=:\n\t"                                                        \
            "mbarrier.try_wait.parity.acquire.cta.shared::cta.b64 P1, [%0], %1, 0x989680;\n\t" \
            "@P1 bra.uni WD_%=;\n\t"                                            \
            "bra.uni WL_%=;\n\t"                                                \
            "WD_%=:\n\t}" :: "r"(_m), "r"(_p) : "memory");                      \
    }                                                                           \
} while (0)

#define MMA_F16(d, a0, a1, a2, a3, b0, b1)                                    \
    asm volatile("mma.sync.aligned.m16n8k16.row.col.f32.f16.f16.f32 "         \
                 "{%0,%1,%2,%3}, {%4,%5,%6,%7}, {%8,%9}, {%0,%1,%2,%3};"      \
                 : "+f"((d)[0]), "+f"((d)[1]), "+f"((d)[2]), "+f"((d)[3])     \
                 : "r"(a0), "r"(a1), "r"(a2), "r"(a3), "r"(b0), "r"(b1))

// ---------------- fused pack kernel (same as R12) ----------------
__global__ void __launch_bounds__(256) pack_fused_kernel(
    const float* __restrict__ a, const int* __restrict__ w)
{
    const int bid  = blockIdx.x;
    const int role = bid & 1;
    const int idx  = bid >> 1;

    if (role == 0) {
        const int rt = idx >> 3;
        const int k0 = (idx & 7) * 512;
        __shared__ __half sh[16][520];

        #pragma unroll
        for (int u = threadIdx.x; u < 2048; u += 256) {
            const int row = u >> 7, c4 = u & 127;
            float4 v = *reinterpret_cast<const float4*>(
                a + (size_t)(rt * 16 + row) * KDIM + k0 + c4 * 4);
            __half2* d = reinterpret_cast<__half2*>(&sh[row][c4 * 4]);
            d[0] = __floats2half2_rn(v.x, v.y);
            d[1] = __floats2half2_rn(v.z, v.w);
        }
        __syncthreads();

        #pragma unroll
        for (int u = threadIdx.x; u < 1024; u += 256) {
            const int kt = u >> 5, lane = u & 31;
            const int g = lane >> 2, t = lane & 3;
            const int kc = kt * 16 + 2 * t;
            uint32_t r0 = *reinterpret_cast<const uint32_t*>(&sh[g][kc]);
            uint32_t r1 = *reinterpret_cast<const uint32_t*>(&sh[g + 8][kc]);
            uint32_t r2 = *reinterpret_cast<const uint32_t*>(&sh[g][kc + 8]);
            uint32_t r3 = *reinterpret_cast<const uint32_t*>(&sh[g + 8][kc + 8]);
            int4* dst = reinterpret_cast<int4*>(
                reinterpret_cast<char*>(g_af)
                + (((size_t)rt * 256 + (k0 >> 4) + kt) << 9) + lane * 16);
            *dst = make_int4(r0, r1, r2, r3);
        }
    } else {
        const int nt = idx >> 3;
        const int k0 = (idx & 7) * 512;
        __shared__ __half shw[8][520];

        #pragma unroll
        for (int u = threadIdx.x; u < 1024; u += 256) {
            const int row = u >> 7, c4 = u & 127;
            int4 v = *reinterpret_cast<const int4*>(
                w + (size_t)(nt * 8 + row) * KDIM + k0 + c4 * 4);
            __half2* d = reinterpret_cast<__half2*>(&shw[row][c4 * 4]);
            d[0] = __floats2half2_rn((float)v.x, (float)v.y);
            d[1] = __floats2half2_rn((float)v.z, (float)v.w);
        }
        __syncthreads();

        #pragma unroll
        for (int u = threadIdx.x; u < 1024; u += 256) {
            const int kt = u >> 5, lane = u & 31;
            const int g = lane >> 2, t = lane & 3;
            const int kc = kt * 16 + 2 * t;
            uint32_t b0 = *reinterpret_cast<const uint32_t*>(&shw[g][kc]);
            uint32_t b1 = *reinterpret_cast<const uint32_t*>(&shw[g][kc + 8]);
            const int ktg = (k0 >> 4) + kt;
            int2* dst = reinterpret_cast<int2*>(
                reinterpret_cast<char*>(g_wf)
                + (((size_t)nt * 128 + (ktg >> 1)) << 9)
                + lane * 16 + (ktg & 1) * 8);
            *dst = make_int2(b0, b1);
        }
    }
}

// ---------------- main GEMM: 128 threads, 4 warps of 64x64 ----------------
__global__ void __launch_bounds__(128, 2) gemm_kernel(
    const float* __restrict__ scales, float* __restrict__ out)
{
    extern __shared__ char smem[];
    const uint32_t sbase = smem_u32(smem);
    const uint32_t stage0 = sbase + HDR_BYTES;

    const int tid  = threadIdx.x;
    const int lane = tid & 31;
    const int wid  = tid >> 5;        // 0..3
    const int wm   = wid >> 1;        // 0..1
    const int wn   = wid & 1;         // 0..1
    const int g    = lane >> 2;
    const int t    = lane & 3;

    // full[s] at sbase + s*8 (count 128, async arrives)
    // empty[s] at sbase + 24 + s*8 (count 4, one arrive per warp)
    if (tid == 0) {
        #pragma unroll
        for (int s = 0; s < 3; s++) {
            MBAR_INIT(sbase + s * 8, 128);
            MBAR_INIT(sbase + 24 + s * 8, 4);
        }
    }
    __syncthreads();

    // grouped-M raster (GROUPM=8, num_n=32)
    const int num_n  = NDIM / BN;
    const int GROUPM = 8;
    const int bid = blockIdx.x;
    const int grp = bid / (GROUPM * num_n);
    const int rem = bid % (GROUPM * num_n);
    const int m0 = (grp * GROUPM + (rem % GROUPM)) * BM;
    const int n0 = (rem / GROUPM) * BN;
    const int rt0 = m0 >> 4;
    const int nt0 = n0 >> 3;

    float acc[4][8][4];
    #pragma unroll
    for (int i = 0; i < 4; i++)
        #pragma unroll
        for (int j = 0; j < 8; j++)
            #pragma unroll
            for (int c = 0; c < 4; c++) acc[i][j][c] = 0.0f;

    const char* gA = reinterpret_cast<const char*>(g_af);
    const char* gB = reinterpret_cast<const char*>(g_wf);

    #define ISSUE_STAGE(kt_, slot_)                                            \
    do {                                                                       \
        const int _kt4 = (kt_) * 4;                                            \
        const uint32_t _sa = stage0 + (uint32_t)(slot_) * STAGE_BYTES;         \
        const uint32_t _sb = _sa + A_ST_BYTES;                                 \
        _Pragma("unroll")                                                      \
        for (int u = tid; u < 1024; u += 128) {                                \
            const int mi = u >> 7;                                             \
            cp_async16(_sa + (u << 4),                                         \
                gA + (((size_t)(rt0 + mi) * 256 + _kt4) << 9)                  \
                   + ((u & 127) << 4));                                        \
        }                                                                      \
        _Pragma("unroll")                                                      \
        for (int u = tid; u < 1024; u += 128) {                                \
            const int nj = u >> 6;                                             \
            cp_async16(_sb + (u << 4),                                         \
                gB + (((size_t)(nt0 + nj) * 128 + (kt_) * 2) << 9)             \
                   + ((u & 63) << 4));                                         \
        }                                                                      \
    } while (0)

    #define ISSUE_CHUNK(kt_, slot_, c_)                                        \
    do {                                                                       \
        const int _kt4 = (kt_) * 4;                                            \
        const uint32_t _sa = stage0 + (uint32_t)(slot_) * STAGE_BYTES;         \
        const uint32_t _sb = _sa + A_ST_BYTES;                                 \
        if ((c_) < 2) {                                                        \
            _Pragma("unroll")                                                  \
            for (int q = 0; q < 4; q++) {                                      \
                const int u = tid + ((c_) * 4 + q) * 128;                      \
                const int mi = u >> 7;                                         \
                cp_async16(_sa + (u << 4),                                     \
                    gA + (((size_t)(rt0 + mi) * 256 + _kt4) << 9)              \
                       + ((u & 127) << 4));                                    \
            }                                                                  \
        } else {                                                               \
            _Pragma("unroll")                                                  \
            for (int q = 0; q < 4; q++) {                                      \
                const int u = tid + (((c_) - 2) * 4 + q) * 128;                \
                const int nj = u >> 6;                                         \
                cp_async16(_sb + (u << 4),                                     \
                    gB + (((size_t)(nt0 + nj) * 128 + (kt_) * 2) << 9)         \
                       + ((u & 63) << 4));                                     \
            }                                                                  \
        }                                                                      \
    } while (0)

    // producer cursor (phase starts flipped), consumer cursor
    int sp = 0, pp = 1;
    int sc = 0, pc = 0;

    // prologue: fill stages 0,1
    #pragma unroll
    for (int kn = 0; kn < 2; kn++) {
        MBAR_WAIT_PARITY(sbase + 24 + sp * 8, pp);   // passes immediately
        ISSUE_STAGE(kn, sp);
        CPASYNC_MBAR_ARRIVE(sbase + sp * 8);
        if (++sp == 3) { sp = 0; pp ^= 1; }
    }

    const uint32_t lane16 = (uint32_t)lane * 16;
    const uint32_t a_warp = (uint32_t)(wm * 4) * 2048;
    const uint32_t b_warp = (uint32_t)(wn * 8) * 1024;

    for (int kt = 0; kt < NKT; kt++) {
        const int kn = kt + 2;
        const bool pre = (kn < NKT);
        const int spc = sp;

        // producer gate: stage spc free? (all-lane read-only poll)
        if (pre) MBAR_WAIT_PARITY(sbase + 24 + spc * 8, pp);
        // consumer gate: data for kt ready?
        MBAR_WAIT_PARITY(sbase + sc * 8, pc);

        const uint32_t sa = stage0 + (uint32_t)sc * STAGE_BYTES;
        const uint32_t sb = sa + A_ST_BYTES;

        uint32_t bf[8][4];

        #pragma unroll
        for (int ks = 0; ks < 4; ks++) {
            if (pre) ISSUE_CHUNK(kn, spc, ks);

            const int h = ks & 1;
            if (h == 0) {
                const int p = ks >> 1;
                #pragma unroll
                for (int j = 0; j < 8; j++) {
                    const uint32_t addr =
                        sb + b_warp + (uint32_t)(j * 1024 + p * 512) + lane16;
                    asm volatile("ld.shared.v4.u32 {%0,%1,%2,%3}, [%4];"
                                 : "=r"(bf[j][0]), "=r"(bf[j][1]),
                                   "=r"(bf[j][2]), "=r"(bf[j][3]) : "r"(addr));
                }
            }
            #pragma unroll
            for (int i = 0; i < 4; i++) {
                uint32_t a0, a1, a2, a3;
                const uint32_t addr =
                    sa + a_warp + (uint32_t)((i * 4 + ks) * 512) + lane16;
                asm volatile("ld.shared.v4.u32 {%0,%1,%2,%3}, [%4];"
                             : "=r"(a0), "=r"(a1), "=r"(a2), "=r"(a3) : "r"(addr));
                #pragma unroll
                for (int j = 0; j < 8; j++)
                    MMA_F16(acc[i][j], a0, a1, a2, a3,
                            bf[j][h * 2], bf[j][h * 2 + 1]);
            }
        }

        if (pre) {
            CPASYNC_MBAR_ARRIVE(sbase + spc * 8);   // async-proxy, per-thread
            if (++sp == 3) { sp = 0; pp ^= 1; }
        }
        // warp done reading stage sc: ONE arrive per warp
        __syncwarp();
        if (lane == 0) MBAR_ARRIVE(sbase + 24 + sc * 8);
        if (++sc == 3) { sc = 0; pc ^= 1; }
    }

    // ---- epilogue: scale and store ----
    const int orow0 = m0 + wm * 64;
    const int ocol0 = n0 + wn * 64;
    #pragma unroll
    for (int j = 0; j < 8; j++) {
        const int col = ocol0 + j * 8 + 2 * t;
        const float2 sc2 = *reinterpret_cast<const float2*>(scales + col);
        #pragma unroll
        for (int i = 0; i < 4; i++) {
            const int row = orow0 + i * 16 + g;
            float2 v0 = { acc[i][j][0] * sc2.x, acc[i][j][1] * sc2.y };
            float2 v1 = { acc[i][j][2] * sc2.x, acc[i][j][3] * sc2.y };
            *reinterpret_cast<float2*>(out + (size_t)row * NDIM + col)       = v0;
            *reinterpret_cast<float2*>(out + (size_t)(row + 8) * NDIM + col) = v1;
        }
    }
}

// ---------------- host ----------------
extern "C" void kernel_launch(void* const* d_in, const int* in_sizes, int n_in,
                              void* d_out, int out_size) {
    const float* input  = (const float*)d_in[0];
    const int*   weight = (const int*)d_in[1];
    const float* scales = (const float*)d_in[2];
    float* out = (float*)d_out;

    pack_fused_kernel<<<8192, 256>>>(input, weight);

    cudaFuncSetAttribute(gemm_kernel,
                         cudaFuncAttributeMaxDynamicSharedMemorySize, SMEM_BYTES);
    const int grid = (MDIM / BM) * (NDIM / BN);   // 2048
    gemm_kernel<<<grid, 128, SMEM_BYTES>>>(scales, out);
}

// round 15
// speedup vs baseline: 1.1054x; 1.1054x over previous
#include <cuda_runtime.h>
#include <cuda_fp16.h>
#include <cstdint>

// ============================================================
// WeightOnlyInt8Linear: out = input @ weight^T * scales
// R15: R12 base + cp.async.bulk stage loads.
//   Pack output re-laid so each CTA-ktile stage slice is ONE
//   contiguous 16KB block per operand ([tile][ktile][16KB]).
//   One elected thread issues 2 cp.async.bulk per stage into a
//   count-1 mbarrier (expect_tx 32K) — deletes 2048 LDGSTS
//   issues + address ALU per CTA-ktile from the warps' streams.
//   Stage-free gating: __syncthreads (R13/R14 proved mbarrier
//   empty-gating loses). Consumer wait: mbarrier parity.
// Rest = R12: warp 64x64, 128-thr CTA, occ 2, CTA 128x128x64,
// 3 stages, paired-B LDS.128.
// ============================================================

static constexpr int MDIM = 8192;
static constexpr int NDIM = 4096;
static constexpr int KDIM = 4096;

static constexpr int BM = 128;
static constexpr int BN = 128;
static constexpr int BK = 64;             // 4 k16 steps
static constexpr int NKT = KDIM / BK;     // 64

static constexpr int A_ST_BYTES = 16384;  // contiguous per (mtile, ktile)
static constexpr int B_ST_BYTES = 16384;  // contiguous per (ntile, ktile)
static constexpr int STAGE_BYTES = A_ST_BYTES + B_ST_BYTES;      // 32768
static constexpr int HDR_BYTES   = 128;
static constexpr int SMEM_BYTES  = HDR_BYTES + 3 * STAGE_BYTES;  // 98432

// static scratch (fragment-major fp16, stage-contiguous)
// A: [mtile(64)][ktile(64)][ mi(8)<<11 | ks(4)<<9 | lane*16 ]  (16KB blocks)
// B: [ntile(32)][ktile(64)][ nj(16)<<10 | p(2)<<9 | lane*16 | h*8 ]
__device__ __half g_af[(size_t)MDIM * KDIM];   // 64 MB
__device__ __half g_wf[(size_t)NDIM * KDIM];   // 32 MB

// ---------------- helpers ----------------
__device__ __forceinline__ uint32_t smem_u32(const void* p) {
    uint32_t a;
    asm("{ .reg .u64 t; cvta.to.shared.u64 t, %1; cvt.u32.u64 %0, t; }"
        : "=r"(a) : "l"(p));
    return a;
}

#define MBAR_INIT(addr, cnt) \
    asm volatile("mbarrier.init.shared.b64 [%0], %1;" :: "r"(addr), "r"(cnt) : "memory")
#define MBAR_EXPECT_TX(addr, bytes) \
    asm volatile("mbarrier.arrive.expect_tx.shared.b64 _, [%0], %1;" \
                 :: "r"(addr), "r"(bytes) : "memory")

#define MBAR_WAIT_PARITY(addr, ph) do {                                         \
    uint32_t _m = (addr); uint32_t _p = (ph); uint32_t _done;                   \
    asm volatile("{\n\t.reg .pred p;\n\t"                                       \
        "mbarrier.try_wait.parity.acquire.cta.shared::cta.b64 p, [%1], %2;\n\t" \
        "selp.b32 %0, 1, 0, p;\n\t}"                                            \
        : "=r"(_done) : "r"(_m), "r"(_p) : "memory");                           \
    if (!_done) {                                                               \
        asm volatile("{\n\t.reg .pred P1;\n\t"                                  \
            "WL_%=:\n\t"                                                        \
            "mbarrier.try_wait.parity.acquire.cta.shared::cta.b64 P1, [%0], %1, 0x989680;\n\t" \
            "@P1 bra.uni WD_%=;\n\t"                                            \
            "bra.uni WL_%=;\n\t"                                                \
            "WD_%=:\n\t}" :: "r"(_m), "r"(_p) : "memory");                      \
    }                                                                           \
} while (0)

__device__ __forceinline__ void cp_bulk(uint32_t dst, const void* src,
                                        uint32_t bytes, uint32_t mbar) {
    asm volatile(
        "cp.async.bulk.shared::cta.global.mbarrier::complete_tx::bytes "
        "[%0], [%1], %2, [%3];"
        :: "r"(dst), "l"(src), "r"(bytes), "r"(mbar) : "memory");
}

#define MMA_F16(d, a0, a1, a2, a3, b0, b1)                                    \
    asm volatile("mma.sync.aligned.m16n8k16.row.col.f32.f16.f16.f32 "         \
                 "{%0,%1,%2,%3}, {%4,%5,%6,%7}, {%8,%9}, {%0,%1,%2,%3};"      \
                 : "+f"((d)[0]), "+f"((d)[1]), "+f"((d)[2]), "+f"((d)[3])     \
                 : "r"(a0), "r"(a1), "r"(a2), "r"(a3), "r"(b0), "r"(b1))

// ---------------- fused pack kernel (stage-contiguous layout) ----------------
__global__ void __launch_bounds__(256) pack_fused_kernel(
    const float* __restrict__ a, const int* __restrict__ w)
{
    const int bid  = blockIdx.x;
    const int role = bid & 1;
    const int idx  = bid >> 1;

    if (role == 0) {
        // ---- A pack: f32 -> f16, [mtile][ktile][mi|ks|lane16] ----
        const int rt = idx >> 3;            // global m16 tile 0..511
        const int k0 = (idx & 7) * 512;
        __shared__ __half sh[16][520];

        #pragma unroll
        for (int u = threadIdx.x; u < 2048; u += 256) {
            const int row = u >> 7, c4 = u & 127;
            float4 v = *reinterpret_cast<const float4*>(
                a + (size_t)(rt * 16 + row) * KDIM + k0 + c4 * 4);
            __half2* d = reinterpret_cast<__half2*>(&sh[row][c4 * 4]);
            d[0] = __floats2half2_rn(v.x, v.y);
            d[1] = __floats2half2_rn(v.z, v.w);
        }
        __syncthreads();

        #pragma unroll
        for (int u = threadIdx.x; u < 1024; u += 256) {
            const int kt = u >> 5, lane = u & 31;
            const int g = lane >> 2, t = lane & 3;
            const int kc = kt * 16 + 2 * t;
            uint32_t r0 = *reinterpret_cast<const uint32_t*>(&sh[g][kc]);
            uint32_t r1 = *reinterpret_cast<const uint32_t*>(&sh[g + 8][kc]);
            uint32_t r2 = *reinterpret_cast<const uint32_t*>(&sh[g][kc + 8]);
            uint32_t r3 = *reinterpret_cast<const uint32_t*>(&sh[g + 8][kc + 8]);
            const int ktg = (k0 >> 4) + kt;           // global k16 0..255
            int4* dst = reinterpret_cast<int4*>(
                reinterpret_cast<char*>(g_af)
                + (((size_t)(rt >> 3) * 64 + (ktg >> 2)) << 14)
                + ((rt & 7) << 11) + ((ktg & 3) << 9) + lane * 16);
            *dst = make_int4(r0, r1, r2, r3);
        }
    } else {
        // ---- W pack: int32 -> f16, [ntile][ktile][nj|p|lane16|h8] ----
        const int nt = idx >> 3;            // global n8 tile 0..511
        const int k0 = (idx & 7) * 512;
        __shared__ __half shw[8][520];

        #pragma unroll
        for (int u = threadIdx.x; u < 1024; u += 256) {
            const int row = u >> 7, c4 = u & 127;
            int4 v = *reinterpret_cast<const int4*>(
                w + (size_t)(nt * 8 + row) * KDIM + k0 + c4 * 4);
            __half2* d = reinterpret_cast<__half2*>(&shw[row][c4 * 4]);
            d[0] = __floats2half2_rn((float)v.x, (float)v.y);
            d[1] = __floats2half2_rn((float)v.z, (float)v.w);
        }
        __syncthreads();

        #pragma unroll
        for (int u = threadIdx.x; u < 1024; u += 256) {
            const int kt = u >> 5, lane = u & 31;
            const int g = lane >> 2, t = lane & 3;
            const int kc = kt * 16 + 2 * t;
            uint32_t b0 = *reinterpret_cast<const uint32_t*>(&shw[g][kc]);
            uint32_t b1 = *reinterpret_cast<const uint32_t*>(&shw[g][kc + 8]);
            const int ktg = (k0 >> 4) + kt;
            int2* dst = reinterpret_cast<int2*>(
                reinterpret_cast<char*>(g_wf)
                + (((size_t)(nt >> 4) * 64 + (ktg >> 2)) << 14)
                + ((nt & 15) << 10) + (((ktg >> 1) & 1) << 9)
                + lane * 16 + (ktg & 1) * 8);
            *dst = make_int2(b0, b1);
        }
    }
}

// ---------------- main GEMM: 128 threads, 4 warps of 64x64 ----------------
__global__ void __launch_bounds__(128, 2) gemm_kernel(
    const float* __restrict__ scales, float* __restrict__ out)
{
    extern __shared__ char smem[];
    const uint32_t sbase = smem_u32(smem);
    const uint32_t stage0 = sbase + HDR_BYTES;

    const int tid  = threadIdx.x;
    const int lane = tid & 31;
    const int wid  = tid >> 5;        // 0..3
    const int wm   = wid >> 1;        // 0..1
    const int wn   = wid & 1;         // 0..1
    const int g    = lane >> 2;
    const int t    = lane & 3;

    // full[s] mbarriers at sbase + s*8, count 1 (expect_tx arrival only)
    if (tid == 0) {
        #pragma unroll
        for (int s = 0; s < 3; s++) MBAR_INIT(sbase + s * 8, 1);
    }
    __syncthreads();

    // grouped-M raster (GROUPM=8, num_n=32)
    const int num_n  = NDIM / BN;
    const int GROUPM = 8;
    const int bid = blockIdx.x;
    const int grp = bid / (GROUPM * num_n);
    const int rem = bid % (GROUPM * num_n);
    const int m0 = (grp * GROUPM + (rem % GROUPM)) * BM;
    const int n0 = (rem / GROUPM) * BN;
    const int mtile = m0 >> 7;        // 0..63
    const int ntile = n0 >> 7;        // 0..31

    const char* gA = reinterpret_cast<const char*>(g_af)
                   + ((size_t)mtile << 20);             // mtile*64*16384
    const char* gB = reinterpret_cast<const char*>(g_wf)
                   + ((size_t)ntile << 20);             // ntile*64*16384

    float acc[4][8][4];
    #pragma unroll
    for (int i = 0; i < 4; i++)
        #pragma unroll
        for (int j = 0; j < 8; j++)
            #pragma unroll
            for (int c = 0; c < 4; c++) acc[i][j][c] = 0.0f;

    // elected producer: issue one stage = expect_tx + 2 bulk copies
    #define ISSUE_STAGE(kt_, slot_)                                            \
    do {                                                                       \
        const uint32_t _mb = sbase + (uint32_t)(slot_) * 8;                    \
        const uint32_t _sa = stage0 + (uint32_t)(slot_) * STAGE_BYTES;         \
        MBAR_EXPECT_TX(_mb, STAGE_BYTES);                                      \
        cp_bulk(_sa,              gA + ((size_t)(kt_) << 14), A_ST_BYTES, _mb);\
        cp_bulk(_sa + A_ST_BYTES, gB + ((size_t)(kt_) << 14), B_ST_BYTES, _mb);\
    } while (0)

    // prologue: fill stages 0,1
    if (tid == 0) {
        ISSUE_STAGE(0, 0);
        ISSUE_STAGE(1, 1);
    }

    int s_cur = 0, pc = 0;   // consumer stage + parity
    int s_nxt = 2;
    const uint32_t lane16 = (uint32_t)lane * 16;
    const uint32_t a_warp = (uint32_t)(wm * 4) * 2048;
    const uint32_t b_warp = (uint32_t)(wn * 8) * 1024;

    for (int kt = 0; kt < NKT; kt++) {
        // all warps finished reading stage s_nxt's old contents (at kt-1)
        __syncthreads();

        const int kn = kt + 2;
        if (kn < NKT && tid == 0) ISSUE_STAGE(kn, s_nxt);

        // consumer: wait for kt's data (acquire)
        MBAR_WAIT_PARITY(sbase + s_cur * 8, pc);

        const uint32_t sa = stage0 + (uint32_t)s_cur * STAGE_BYTES;
        const uint32_t sb = sa + A_ST_BYTES;

        uint32_t bf[8][4];

        #pragma unroll
        for (int ks = 0; ks < 4; ks++) {
            const int h = ks & 1;
            if (h == 0) {
                const int p = ks >> 1;
                #pragma unroll
                for (int j = 0; j < 8; j++) {
                    const uint32_t addr =
                        sb + b_warp + (uint32_t)(j * 1024 + p * 512) + lane16;
                    asm volatile("ld.shared.v4.u32 {%0,%1,%2,%3}, [%4];"
                                 : "=r"(bf[j][0]), "=r"(bf[j][1]),
                                   "=r"(bf[j][2]), "=r"(bf[j][3]) : "r"(addr));
                }
            }
            #pragma unroll
            for (int i = 0; i < 4; i++) {
                uint32_t a0, a1, a2, a3;
                const uint32_t addr =
                    sa + a_warp + (uint32_t)((i * 4 + ks) * 512) + lane16;
                asm volatile("ld.shared.v4.u32 {%0,%1,%2,%3}, [%4];"
                             : "=r"(a0), "=r"(a1), "=r"(a2), "=r"(a3) : "r"(addr));
                #pragma unroll
                for (int j = 0; j < 8; j++)
                    MMA_F16(acc[i][j], a0, a1, a2, a3,
                            bf[j][h * 2], bf[j][h * 2 + 1]);
            }
        }

        s_nxt = (s_nxt == 2) ? 0 : s_nxt + 1;
        if (++s_cur == 3) { s_cur = 0; pc ^= 1; }
    }

    // ---- epilogue: scale and store ----
    const int orow0 = m0 + wm * 64;
    const int ocol0 = n0 + wn * 64;
    #pragma unroll
    for (int j = 0; j < 8; j++) {
        const int col = ocol0 + j * 8 + 2 * t;
        const float2 sc2 = *reinterpret_cast<const float2*>(scales + col);
        #pragma unroll
        for (int i = 0; i < 4; i++) {
            const int row = orow0 + i * 16 + g;
            float2 v0 = { acc[i][j][0] * sc2.x, acc[i][j][1] * sc2.y };
            float2 v1 = { acc[i][j][2] * sc2.x, acc[i][j][3] * sc2.y };
            *reinterpret_cast<float2*>(out + (size_t)row * NDIM + col)       = v0;
            *reinterpret_cast<float2*>(out + (size_t)(row + 8) * NDIM + col) = v1;
        }
    }
}

// ---------------- host ----------------
extern "C" void kernel_launch(void* const* d_in, const int* in_sizes, int n_in,
                              void* d_out, int out_size) {
    const float* input  = (const float*)d_in[0];
    const int*   weight = (const int*)d_in[1];
    const float* scales = (const float*)d_in[2];
    float* out = (float*)d_out;

    pack_fused_kernel<<<8192, 256>>>(input, weight);

    cudaFuncSetAttribute(gemm_kernel,
                         cudaFuncAttributeMaxDynamicSharedMemorySize, SMEM_BYTES);
    const int grid = (MDIM / BM) * (NDIM / BN);   // 2048
    gemm_kernel<<<grid, 128, SMEM_BYTES>>>(scales, out);
}

// round 16
// speedup vs baseline: 1.1249x; 1.0176x over previous
#include <cuda_runtime.h>
#include <cuda_fp16.h>
#include <cstdint>

// ============================================================
// WeightOnlyInt8Linear: out = input @ weight^T * scales
// R16: R15 + (a) leader-wait: warp 0 TRYWAITs the full-barrier
// BEFORE __syncthreads, barrier broadcasts readiness (3/4 warps
// skip the 90-cyc fast-path); (b) kt loop unrolled x3 so stage
// ring indices and parity are compile-time per copy.
// Core = R15: cp.async.bulk single-thread stage loads (2 UBLKCP
// vs 2048 LDGSTS), warp 64x64, 128-thr CTA, occ 2, 128x128x64,
// 3 stages, paired-B LDS.128, fused stage-contiguous pack.
// ============================================================

static constexpr int MDIM = 8192;
static constexpr int NDIM = 4096;
static constexpr int KDIM = 4096;

static constexpr int BM = 128;
static constexpr int BN = 128;
static constexpr int BK = 64;             // 4 k16 steps
static constexpr int NKT = KDIM / BK;     // 64 (divisible by 3-unroll? no: handled by 63+1... use 64 = 21*3+1 -> peel)
static constexpr int A_ST_BYTES = 16384;
static constexpr int B_ST_BYTES = 16384;
static constexpr int STAGE_BYTES = A_ST_BYTES + B_ST_BYTES;      // 32768
static constexpr int HDR_BYTES   = 128;
static constexpr int SMEM_BYTES  = HDR_BYTES + 3 * STAGE_BYTES;  // 98432

// static scratch (fragment-major fp16, stage-contiguous)
__device__ __half g_af[(size_t)MDIM * KDIM];   // 64 MB
__device__ __half g_wf[(size_t)NDIM * KDIM];   // 32 MB

// ---------------- helpers ----------------
__device__ __forceinline__ uint32_t smem_u32(const void* p) {
    uint32_t a;
    asm("{ .reg .u64 t; cvta.to.shared.u64 t, %1; cvt.u32.u64 %0, t; }"
        : "=r"(a) : "l"(p));
    return a;
}

#define MBAR_INIT(addr, cnt) \
    asm volatile("mbarrier.init.shared.b64 [%0], %1;" :: "r"(addr), "r"(cnt) : "memory")
#define MBAR_EXPECT_TX(addr, bytes) \
    asm volatile("mbarrier.arrive.expect_tx.shared.b64 _, [%0], %1;" \
                 :: "r"(addr), "r"(bytes) : "memory")

#define MBAR_WAIT_PARITY(addr, ph) do {                                         \
    uint32_t _m = (addr); uint32_t _p = (ph); uint32_t _done;                   \
    asm volatile("{\n\t.reg .pred p;\n\t"                                       \
        "mbarrier.try_wait.parity.acquire.cta.shared::cta.b64 p, [%1], %2;\n\t" \
        "selp.b32 %0, 1, 0, p;\n\t}"                                            \
        : "=r"(_done) : "r"(_m), "r"(_p) : "memory");                           \
    if (!_done) {                                                               \
        asm volatile("{\n\t.reg .pred P1;\n\t"                                  \
            "WL_%=:\n\t"                                                        \
            "mbarrier.try_wait.parity.acquire.cta.shared::cta.b64 P1, [%0], %1, 0x989680;\n\t" \
            "@P1 bra.uni WD_%=;\n\t"                                            \
            "bra.uni WL_%=;\n\t"                                                \
            "WD_%=:\n\t}" :: "r"(_m), "r"(_p) : "memory");                      \
    }                                                                           \
} while (0)

__device__ __forceinline__ void cp_bulk(uint32_t dst, const void* src,
                                        uint32_t bytes, uint32_t mbar) {
    asm volatile(
        "cp.async.bulk.shared::cta.global.mbarrier::complete_tx::bytes "
        "[%0], [%1], %2, [%3];"
        :: "r"(dst), "l"(src), "r"(bytes), "r"(mbar) : "memory");
}

#define MMA_F16(d, a0, a1, a2, a3, b0, b1)                                    \
    asm volatile("mma.sync.aligned.m16n8k16.row.col.f32.f16.f16.f32 "         \
                 "{%0,%1,%2,%3}, {%4,%5,%6,%7}, {%8,%9}, {%0,%1,%2,%3};"      \
                 : "+f"((d)[0]), "+f"((d)[1]), "+f"((d)[2]), "+f"((d)[3])     \
                 : "r"(a0), "r"(a1), "r"(a2), "r"(a3), "r"(b0), "r"(b1))

// ---------------- fused pack kernel (stage-contiguous layout, = R15) --------
__global__ void __launch_bounds__(256) pack_fused_kernel(
    const float* __restrict__ a, const int* __restrict__ w)
{
    const int bid  = blockIdx.x;
    const int role = bid & 1;
    const int idx  = bid >> 1;

    if (role == 0) {
        const int rt = idx >> 3;
        const int k0 = (idx & 7) * 512;
        __shared__ __half sh[16][520];

        #pragma unroll
        for (int u = threadIdx.x; u < 2048; u += 256) {
            const int row = u >> 7, c4 = u & 127;
            float4 v = *reinterpret_cast<const float4*>(
                a + (size_t)(rt * 16 + row) * KDIM + k0 + c4 * 4);
            __half2* d = reinterpret_cast<__half2*>(&sh[row][c4 * 4]);
            d[0] = __floats2half2_rn(v.x, v.y);
            d[1] = __floats2half2_rn(v.z, v.w);
        }
        __syncthreads();

        #pragma unroll
        for (int u = threadIdx.x; u < 1024; u += 256) {
            const int kt = u >> 5, lane = u & 31;
            const int g = lane >> 2, t = lane & 3;
            const int kc = kt * 16 + 2 * t;
            uint32_t r0 = *reinterpret_cast<const uint32_t*>(&sh[g][kc]);
            uint32_t r1 = *reinterpret_cast<const uint32_t*>(&sh[g + 8][kc]);
            uint32_t r2 = *reinterpret_cast<const uint32_t*>(&sh[g][kc + 8]);
            uint32_t r3 = *reinterpret_cast<const uint32_t*>(&sh[g + 8][kc + 8]);
            const int ktg = (k0 >> 4) + kt;
            int4* dst = reinterpret_cast<int4*>(
                reinterpret_cast<char*>(g_af)
                + (((size_t)(rt >> 3) * 64 + (ktg >> 2)) << 14)
                + ((rt & 7) << 11) + ((ktg & 3) << 9) + lane * 16);
            *dst = make_int4(r0, r1, r2, r3);
        }
    } else {
        const int nt = idx >> 3;
        const int k0 = (idx & 7) * 512;
        __shared__ __half shw[8][520];

        #pragma unroll
        for (int u = threadIdx.x; u < 1024; u += 256) {
            const int row = u >> 7, c4 = u & 127;
            int4 v = *reinterpret_cast<const int4*>(
                w + (size_t)(nt * 8 + row) * KDIM + k0 + c4 * 4);
            __half2* d = reinterpret_cast<__half2*>(&shw[row][c4 * 4]);
            d[0] = __floats2half2_rn((float)v.x, (float)v.y);
            d[1] = __floats2half2_rn((float)v.z, (float)v.w);
        }
        __syncthreads();

        #pragma unroll
        for (int u = threadIdx.x; u < 1024; u += 256) {
            const int kt = u >> 5, lane = u & 31;
            const int g = lane >> 2, t = lane & 3;
            const int kc = kt * 16 + 2 * t;
            uint32_t b0 = *reinterpret_cast<const uint32_t*>(&shw[g][kc]);
            uint32_t b1 = *reinterpret_cast<const uint32_t*>(&shw[g][kc + 8]);
            const int ktg = (k0 >> 4) + kt;
            int2* dst = reinterpret_cast<int2*>(
                reinterpret_cast<char*>(g_wf)
                + (((size_t)(nt >> 4) * 64 + (ktg >> 2)) << 14)
                + ((nt & 15) << 10) + (((ktg >> 1) & 1) << 9)
                + lane * 16 + (ktg & 1) * 8);
            *dst = make_int2(b0, b1);
        }
    }
}

// ---------------- main GEMM: 128 threads, 4 warps of 64x64 ----------------
__global__ void __launch_bounds__(128, 2) gemm_kernel(
    const float* __restrict__ scales, float* __restrict__ out)
{
    extern __shared__ char smem[];
    const uint32_t sbase = smem_u32(smem);
    const uint32_t stage0 = sbase + HDR_BYTES;

    const int tid  = threadIdx.x;
    const int lane = tid & 31;
    const int wid  = tid >> 5;        // 0..3
    const int wm   = wid >> 1;
    const int wn   = wid & 1;
    const int g    = lane >> 2;
    const int t    = lane & 3;

    if (tid == 0) {
        #pragma unroll
        for (int s = 0; s < 3; s++) MBAR_INIT(sbase + s * 8, 1);
    }
    __syncthreads();

    // grouped-M raster (GROUPM=8, num_n=32)
    const int num_n  = NDIM / BN;
    const int GROUPM = 8;
    const int bid = blockIdx.x;
    const int grp = bid / (GROUPM * num_n);
    const int rem = bid % (GROUPM * num_n);
    const int m0 = (grp * GROUPM + (rem % GROUPM)) * BM;
    const int n0 = (rem / GROUPM) * BN;
    const int mtile = m0 >> 7;
    const int ntile = n0 >> 7;

    const char* gA = reinterpret_cast<const char*>(g_af) + ((size_t)mtile << 20);
    const char* gB = reinterpret_cast<const char*>(g_wf) + ((size_t)ntile << 20);

    float acc[4][8][4];
    #pragma unroll
    for (int i = 0; i < 4; i++)
        #pragma unroll
        for (int j = 0; j < 8; j++)
            #pragma unroll
            for (int c = 0; c < 4; c++) acc[i][j][c] = 0.0f;

    #define ISSUE_STAGE(kt_, slot_)                                            \
    do {                                                                       \
        const uint32_t _mb = sbase + (uint32_t)(slot_) * 8;                    \
        const uint32_t _sa = stage0 + (uint32_t)(slot_) * STAGE_BYTES;         \
        MBAR_EXPECT_TX(_mb, STAGE_BYTES);                                      \
        cp_bulk(_sa,              gA + ((size_t)(kt_) << 14), A_ST_BYTES, _mb);\
        cp_bulk(_sa + A_ST_BYTES, gB + ((size_t)(kt_) << 14), B_ST_BYTES, _mb);\
    } while (0)

    if (tid == 0) {
        ISSUE_STAGE(0, 0);
        ISSUE_STAGE(1, 1);
    }

    const uint32_t lane16 = (uint32_t)lane * 16;
    const uint32_t a_warp = (uint32_t)(wm * 4) * 2048;
    const uint32_t b_warp = (uint32_t)(wn * 8) * 1024;

    // one ktile body with compile-time stage slot + parity.
    // order: leader (warp 0) acquires full[slot]; __syncthreads broadcasts
    // readiness AND guarantees all warps done reading the stage being
    // overwritten; tid 0 then issues the kn prefetch.
    #define KTILE_BODY(kt_, slot_, ph_)                                        \
    do {                                                                       \
        if (wid == 0) MBAR_WAIT_PARITY(sbase + (slot_) * 8, (ph_));            \
        __syncthreads();                                                       \
        {                                                                      \
            const int _kn = (kt_) + 2;                                         \
            if (_kn < NKT && tid == 0)                                         \
                ISSUE_STAGE(_kn, ((slot_) + 2) % 3);                           \
        }                                                                      \
        const uint32_t sa = stage0 + (uint32_t)(slot_) * STAGE_BYTES;          \
        const uint32_t sb = sa + A_ST_BYTES;                                   \
        uint32_t bf[8][4];                                                     \
        _Pragma("unroll")                                                      \
        for (int ks = 0; ks < 4; ks++) {                                       \
            const int h = ks & 1;                                              \
            if (h == 0) {                                                      \
                const int p = ks >> 1;                                         \
                _Pragma("unroll")                                              \
                for (int j = 0; j < 8; j++) {                                  \
                    const uint32_t addr =                                      \
                        sb + b_warp + (uint32_t)(j * 1024 + p * 512) + lane16; \
                    asm volatile("ld.shared.v4.u32 {%0,%1,%2,%3}, [%4];"       \
                                 : "=r"(bf[j][0]), "=r"(bf[j][1]),             \
                                   "=r"(bf[j][2]), "=r"(bf[j][3]) : "r"(addr));\
                }                                                              \
            }                                                                  \
            _Pragma("unroll")                                                  \
            for (int i = 0; i < 4; i++) {                                      \
                uint32_t a0, a1, a2, a3;                                       \
                const uint32_t addr =                                          \
                    sa + a_warp + (uint32_t)((i * 4 + ks) * 512) + lane16;     \
                asm volatile("ld.shared.v4.u32 {%0,%1,%2,%3}, [%4];"           \
                             : "=r"(a0), "=r"(a1), "=r"(a2), "=r"(a3)          \
                             : "r"(addr));                                     \
                _Pragma("unroll")                                              \
                for (int j = 0; j < 8; j++)                                    \
                    MMA_F16(acc[i][j], a0, a1, a2, a3,                         \
                            bf[j][h * 2], bf[j][h * 2 + 1]);                   \
            }                                                                  \
        }                                                                      \
    } while (0)

    // NKT = 64 = 21*3 + 1: unrolled-by-3 main loop + one peeled tail.
    // parity for stage s at visit v (kt = 3v + s_off): flips every 3 ktiles.
    #pragma unroll 1
    for (int v = 0; v < 21; v++) {
        const int kt0 = v * 3;
        const uint32_t ph = (uint32_t)(v & 1);
        KTILE_BODY(kt0 + 0, 0, ph);
        KTILE_BODY(kt0 + 1, 1, ph);
        KTILE_BODY(kt0 + 2, 2, ph);
    }
    KTILE_BODY(63, 0, 1);   // kt=63 -> slot 0, visit 21 -> parity 1

    // ---- epilogue: scale and store ----
    const int orow0 = m0 + wm * 64;
    const int ocol0 = n0 + wn * 64;
    #pragma unroll
    for (int j = 0; j < 8; j++) {
        const int col = ocol0 + j * 8 + 2 * t;
        const float2 sc2 = *reinterpret_cast<const float2*>(scales + col);
        #pragma unroll
        for (int i = 0; i < 4; i++) {
            const int row = orow0 + i * 16 + g;
            float2 v0 = { acc[i][j][0] * sc2.x, acc[i][j][1] * sc2.y };
            float2 v1 = { acc[i][j][2] * sc2.x, acc[i][j][3] * sc2.y };
            *reinterpret_cast<float2*>(out + (size_t)row * NDIM + col)       = v0;
            *reinterpret_cast<float2*>(out + (size_t)(row + 8) * NDIM + col) = v1;
        }
    }
}

// ---------------- host ----------------
extern "C" void kernel_launch(void* const* d_in, const int* in_sizes, int n_in,
                              void* d_out, int out_size) {
    const float* input  = (const float*)d_in[0];
    const int*   weight = (const int*)d_in[1];
    const float* scales = (const float*)d_in[2];
    float* out = (float*)d_out;

    pack_fused_kernel<<<8192, 256>>>(input, weight);

    cudaFuncSetAttribute(gemm_kernel,
                         cudaFuncAttributeMaxDynamicSharedMemorySize, SMEM_BYTES);
    const int grid = (MDIM / BM) * (NDIM / BN);   // 2048
    gemm_kernel<<<grid, 128, SMEM_BYTES>>>(scales, out);
}